// round 1
// baseline (speedup 1.0000x reference)
#include <cuda_runtime.h>
#include <stdint.h>

// Problem shapes (fixed by the dataset).
#define BB 64
#define PP 2048
#define GG 512

// Scratch (no allocations allowed in kernel_launch).
__device__ float g_best_iou[BB * PP];
__device__ int   g_best_g[BB * PP];
__device__ float g_ap[BB];

// ---------------------------------------------------------------------------
// K1: per (image, prediction) compute argmax_g IoU(pred, gt_g) with
// first-max tie-break (strict greater running compare), plus the max value.
// ---------------------------------------------------------------------------
__global__ __launch_bounds__(128) void k_bestiou(
    const float* __restrict__ pred_boxes,   // [B,P,4] xywh
    const float* __restrict__ gt_boxes)     // [B,G,4] xywh
{
    const int b = blockIdx.y;
    const int p = blockIdx.x * 128 + threadIdx.x;

    __shared__ float4 sbox[GG];   // x1,y1,x2,y2
    __shared__ float  sarea[GG];

    const float4* gbp = reinterpret_cast<const float4*>(gt_boxes + (size_t)b * GG * 4);
    for (int g = threadIdx.x; g < GG; g += 128) {
        float4 v = gbp[g];
        float x2 = v.x + v.z;
        float y2 = v.y + v.w;
        sbox[g]  = make_float4(v.x, v.y, x2, y2);
        sarea[g] = fabsf((x2 - v.x) * (y2 - v.y));
    }
    __syncthreads();

    float4 pbx = reinterpret_cast<const float4*>(pred_boxes + (size_t)b * PP * 4)[p];
    const float px1 = pbx.x, py1 = pbx.y;
    const float px2 = pbx.x + pbx.z, py2 = pbx.y + pbx.w;
    const float pa  = fabsf((px2 - px1) * (py2 - py1));

    float best = -1.0f;
    int   bg   = 0;

#pragma unroll 4
    for (int g = 0; g < GG; ++g) {
        float4 gb = sbox[g];
        float ix1 = fmaxf(px1, gb.x);
        float iy1 = fmaxf(py1, gb.y);
        float ix2 = fminf(px2, gb.z);
        float iy2 = fminf(py2, gb.w);
        float iw  = fmaxf(ix2 - ix1, 0.0f);
        float ih  = fmaxf(iy2 - iy1, 0.0f);
        float inter = iw * ih;
        float u  = pa + sarea[g] - inter + 1e-9f;
        float iou = __fdividef(inter, u);
        if (iou > best) { best = iou; bg = g; }   // strict > keeps FIRST max
    }

    g_best_iou[b * PP + p] = best;
    g_best_g[b * PP + p]   = bg;
}

// ---------------------------------------------------------------------------
// K2: per image — stable descending sort of scores (bitonic on packed keys),
// greedy TP via min-rank-per-gt (shared atomicMin), prefix sum, AP.
// ---------------------------------------------------------------------------
__global__ __launch_bounds__(512) void k_ap(
    const float* __restrict__ pred_scores,   // [B,P]
    const int*   __restrict__ pred_classes,  // [B,P]
    const int*   __restrict__ gt_classes)    // [B,G]
{
    const int b   = blockIdx.x;
    const int tid = threadIdx.x;

    __shared__ unsigned long long skey[PP];   // (score_bits<<32) | (~idx)
    __shared__ unsigned short     sgc[PP];    // bit15 = cand, low bits = g
    __shared__ int                smin[GG];   // min tp-candidate rank per gt
    __shared__ int                wsum[16];
    __shared__ float              wred[16];

    // Build keys. scores >= 0 so raw float bits are order-monotonic.
    // (~idx) in low bits => equal scores sort smaller idx first (stable argsort).
    for (int i = tid; i < PP; i += 512) {
        unsigned int sb = __float_as_uint(pred_scores[b * PP + i]);
        skey[i] = ((unsigned long long)sb << 32) | (unsigned int)(0xFFFFFFFFu - i);
    }
    for (int g = tid; g < GG; g += 512) smin[g] = 0x7FFFFFFF;
    __syncthreads();

    // Bitonic sort, descending.
    for (int k = 2; k <= PP; k <<= 1) {
        for (int j = k >> 1; j > 0; j >>= 1) {
            for (int t = tid; t < PP / 2; t += 512) {
                int i   = ((t & ~(j - 1)) << 1) | (t & (j - 1));
                int ixj = i | j;
                bool desc = ((i & k) == 0);
                unsigned long long a = skey[i];
                unsigned long long c = skey[ixj];
                bool sw = desc ? (a < c) : (a > c);
                if (sw) { skey[i] = c; skey[ixj] = a; }
            }
            __syncthreads();
        }
    }

    // Candidates + min rank per gt.
    for (int r = tid; r < PP; r += 512) {
        int p = (int)(0xFFFFFFFFu - (unsigned int)(skey[r] & 0xFFFFFFFFu));
        int g = g_best_g[b * PP + p];
        float biou = g_best_iou[b * PP + p];
        bool cand = (biou > 0.5f) && (pred_classes[b * PP + p] == gt_classes[b * GG + g]);
        sgc[r] = (unsigned short)(g | (cand ? 0x8000 : 0));
        if (cand) atomicMin(&smin[g], r);
    }
    __syncthreads();

    // tp[rank] = cand && (rank is the first candidate rank for its gt).
    const int base = tid * 4;
    int t0, t1, t2, t3;
    {
        unsigned short v;
        v = sgc[base + 0]; t0 = ((v & 0x8000) && smin[v & 0x7FFF] == base + 0) ? 1 : 0;
        v = sgc[base + 1]; t1 = ((v & 0x8000) && smin[v & 0x7FFF] == base + 1) ? 1 : 0;
        v = sgc[base + 2]; t2 = ((v & 0x8000) && smin[v & 0x7FFF] == base + 2) ? 1 : 0;
        v = sgc[base + 3]; t3 = ((v & 0x8000) && smin[v & 0x7FFF] == base + 3) ? 1 : 0;
    }
    int lsum = t0 + t1 + t2 + t3;

    // Block inclusive scan of per-thread sums.
    const int lane = tid & 31, wid = tid >> 5;
    int sc = lsum;
    for (int o = 1; o < 32; o <<= 1) {
        int v = __shfl_up_sync(0xFFFFFFFFu, sc, o);
        if (lane >= o) sc += v;
    }
    if (lane == 31) wsum[wid] = sc;
    __syncthreads();
    if (wid == 0 && lane < 16) {
        int v = wsum[lane];
        for (int o = 1; o < 16; o <<= 1) {
            int u = __shfl_up_sync(0xFFFFu, v, o);
            if (lane >= o) v += u;
        }
        wsum[lane] = v;
    }
    __syncthreads();
    int j = (sc - lsum) + (wid > 0 ? wsum[wid - 1] : 0);   // exclusive tp count

    // AP contributions: at tp rank k (1-indexed), j_inc = tp_cum[k]:
    //   0.5 * ( j/k + (k==1 ? 1 : (j-1)/(k-1)) ) ; recall step is 1/G.
    float term = 0.0f;
    int ks = base + 1;
    if (t0) { ++j; term += 0.5f * ((float)j / (float)ks + ((ks == 1) ? 1.0f : (float)(j - 1) / (float)(ks - 1))); }
    ++ks;
    if (t1) { ++j; term += 0.5f * ((float)j / (float)ks + (float)(j - 1) / (float)(ks - 1)); }
    ++ks;
    if (t2) { ++j; term += 0.5f * ((float)j / (float)ks + (float)(j - 1) / (float)(ks - 1)); }
    ++ks;
    if (t3) { ++j; term += 0.5f * ((float)j / (float)ks + (float)(j - 1) / (float)(ks - 1)); }

    // Block reduce term sum.
    float ts = term;
    for (int o = 16; o > 0; o >>= 1) ts += __shfl_down_sync(0xFFFFFFFFu, ts, o);
    if (lane == 0) wred[wid] = ts;
    __syncthreads();
    if (wid == 0 && lane < 16) {
        float v = wred[lane];
        for (int o = 8; o > 0; o >>= 1) v += __shfl_down_sync(0xFFFFu, v, o);
        if (lane == 0) g_ap[b] = v / (float)GG;
    }
}

// ---------------------------------------------------------------------------
// K3: deterministic mean of 64 per-image APs (fixed shuffle tree, no atomics).
// ---------------------------------------------------------------------------
__global__ void k_mean(float* __restrict__ out)
{
    int lane = threadIdx.x;   // one warp
    float v = g_ap[lane] + g_ap[lane + 32];
    for (int o = 16; o > 0; o >>= 1) v += __shfl_down_sync(0xFFFFFFFFu, v, o);
    if (lane == 0) out[0] = v * (1.0f / (float)BB);
}

// ---------------------------------------------------------------------------
extern "C" void kernel_launch(void* const* d_in, const int* in_sizes, int n_in,
                              void* d_out, int out_size)
{
    const float* pred_boxes   = (const float*)d_in[0];
    const float* pred_scores  = (const float*)d_in[1];
    const int*   pred_classes = (const int*)d_in[2];
    const float* gt_boxes     = (const float*)d_in[3];
    const int*   gt_classes   = (const int*)d_in[4];
    float* out = (float*)d_out;

    dim3 g1(PP / 128, BB);
    k_bestiou<<<g1, 128>>>(pred_boxes, gt_boxes);
    k_ap<<<BB, 512>>>(pred_scores, pred_classes, gt_classes);
    k_mean<<<1, 32>>>(out);
}